// round 2
// baseline (speedup 1.0000x reference)
#include <cuda_runtime.h>

#define B 64
#define N 1024
#define D 14
#define HDP 8          // head dim padded 7 -> 8
#define SEPS 1e-10f

// ---------------- device scratch (static globals: allowed) ----------------
__device__ float g_P0[(size_t)B * N * N];        // 256 MB: (avg_attn + eps)^10
__device__ float g_Q[B * 2 * N * HDP];           // (b,h,n,8)
__device__ float g_K[B * 2 * N * HDP];
__device__ float g_V[B * 2 * N * HDP];
__device__ float g_r[B * N];
__device__ float g_c[B * N];
__device__ float g_vpart[8 * B * N];             // deterministic col-sum partials

// ---------------- helpers ----------------
__device__ __forceinline__ float dot8(float4 a, float4 b, float4 c, float4 d) {
    return fmaf(a.x, b.x, fmaf(a.y, b.y, fmaf(a.z, b.z, fmaf(a.w, b.w,
           fmaf(c.x, d.x, fmaf(c.y, d.y, fmaf(c.z, d.z, c.w * d.w)))))));
}
__device__ __forceinline__ float4 fma4(float s, float4 v, float4 acc) {
    acc.x = fmaf(s, v.x, acc.x); acc.y = fmaf(s, v.y, acc.y);
    acc.z = fmaf(s, v.z, acc.z); acc.w = fmaf(s, v.w, acc.w);
    return acc;
}

// ---------------- kernel 1: QKV projection ----------------
__global__ void qkv_kernel(const float* __restrict__ x,
                           const float* __restrict__ Wq, const float* __restrict__ bq,
                           const float* __restrict__ Wk, const float* __restrict__ bk,
                           const float* __restrict__ Wv, const float* __restrict__ bv) {
    __shared__ float w[3 * 196 + 3 * 14];
    int tid = threadIdx.x;
    for (int k = tid; k < 196; k += blockDim.x) {
        w[k] = Wq[k]; w[196 + k] = Wk[k]; w[392 + k] = Wv[k];
    }
    if (tid < 14) { w[588 + tid] = bq[tid]; w[602 + tid] = bk[tid]; w[616 + tid] = bv[tid]; }
    __syncthreads();

    int t = blockIdx.x * blockDim.x + tid;          // token index over B*N
    int b = t >> 10, i = t & 1023;
    float xv[14];
#pragma unroll
    for (int f = 0; f < 14; f++) xv[f] = x[(size_t)t * 14 + f];

#pragma unroll
    for (int e = 0; e < 14; e++) {
        float q = w[588 + e], k = w[602 + e], v = w[616 + e];
#pragma unroll
        for (int f = 0; f < 14; f++) {
            q = fmaf(w[e * 14 + f],       xv[f], q);
            k = fmaf(w[196 + e * 14 + f], xv[f], k);
            v = fmaf(w[392 + e * 14 + f], xv[f], v);
        }
        int h = e / 7, eh = e - h * 7;
        size_t idx = (((size_t)b * 2 + h) * N + i) * HDP + eh;
        g_Q[idx] = q; g_K[idx] = k; g_V[idx] = v;
    }
#pragma unroll
    for (int h = 0; h < 2; h++) {
        size_t idx = (((size_t)b * 2 + h) * N + i) * HDP + 7;
        g_Q[idx] = 0.f; g_K[idx] = 0.f; g_V[idx] = 0.f;
    }
}

// ---------------- kernel 2: fused attention + entropy/cert + P0 + out proj ----------------
// grid (8, 64), block 128. One lane owns one query row; K/V reads are warp-uniform.
__global__ __launch_bounds__(128) void attn_kernel(const float* __restrict__ cert,
                                                   const float* __restrict__ Wo,
                                                   const float* __restrict__ bo,
                                                   float* __restrict__ out,
                                                   float* __restrict__ out_cert) {
    __shared__ float sWo[196];
    __shared__ float sbo[16];
    __shared__ float stg[4][32][33];   // coalescing stage for P0 writes

    int tid = threadIdx.x, w = tid >> 5, lane = tid & 31;
    for (int k = tid; k < 196; k += 128) sWo[k] = Wo[k];
    if (tid < 14) sbo[tid] = bo[tid];
    __syncthreads();

    int b = blockIdx.y;
    int i = blockIdx.x * 128 + w * 32 + lane;

    const float4* Kb = (const float4*)(g_K + (size_t)b * 16384);
    const float4* Vb = (const float4*)(g_V + (size_t)b * 16384);
    const float4* Qb = (const float4*)(g_Q + (size_t)b * 16384);

    const float sc = rsqrtf(7.0f);
    float4 q0a = Qb[2 * i], q0b = Qb[2 * i + 1];
    float4 q1a = Qb[2048 + 2 * i], q1b = Qb[2048 + 2 * i + 1];
    q0a.x *= sc; q0a.y *= sc; q0a.z *= sc; q0a.w *= sc;
    q0b.x *= sc; q0b.y *= sc; q0b.z *= sc; q0b.w *= sc;
    q1a.x *= sc; q1a.y *= sc; q1a.z *= sc; q1a.w *= sc;
    q1b.x *= sc; q1b.y *= sc; q1b.z *= sc; q1b.w *= sc;

    // pass 1: softmax denominators (scores ~N(0,1): exp without max-shift is safe)
    float Z0 = 0.f, Z1 = 0.f;
#pragma unroll 2
    for (int j = 0; j < 1024; j++) {
        Z0 += __expf(dot8(q0a, Kb[2 * j], q0b, Kb[2 * j + 1]));
        Z1 += __expf(dot8(q1a, Kb[2048 + 2 * j], q1b, Kb[2048 + 2 * j + 1]));
    }
    float inv0 = 1.f / Z0, inv1 = 1.f / Z1;

    // pass 2: probs, entropy, P0 = (avg+eps)^10, attn @ V
    float4 a0 = make_float4(0.f, 0.f, 0.f, 0.f), b0v = a0, a1 = a0, b1v = a0;
    float ent = 0.f;
    float* srow = &stg[w][lane][0];
    size_t prow_base = ((size_t)b * N + (size_t)blockIdx.x * 128 + w * 32) * N;

    for (int jc = 0; jc < 1024; jc += 32) {
#pragma unroll 4
        for (int jj = 0; jj < 32; jj++) {
            int j = jc + jj;
            float p0 = __expf(dot8(q0a, Kb[2 * j], q0b, Kb[2 * j + 1])) * inv0;
            float p1 = __expf(dot8(q1a, Kb[2048 + 2 * j], q1b, Kb[2048 + 2 * j + 1])) * inv1;
            float a = 0.5f * (p0 + p1);
            float t = a + SEPS;
            ent -= a * __logf(t);
            float t2 = t * t;
            float t4 = t2 * t2;
            srow[jj] = t4 * t4 * t2;          // t^10
            a0  = fma4(p0, Vb[2 * j], a0);
            b0v = fma4(p0, Vb[2 * j + 1], b0v);
            a1  = fma4(p1, Vb[2048 + 2 * j], a1);
            b1v = fma4(p1, Vb[2048 + 2 * j + 1], b1v);
        }
        __syncwarp();
#pragma unroll 8
        for (int r = 0; r < 32; r++)
            g_P0[prow_base + (size_t)r * N + jc + lane] = stg[w][r][lane];
        __syncwarp();
    }

    // epilogue: out = pre @ Wo.T + bo ; certainty update
    float pre[14] = {a0.x, a0.y, a0.z, a0.w, b0v.x, b0v.y, b0v.z,
                     a1.x, a1.y, a1.z, a1.w, b1v.x, b1v.y, b1v.z};
    float* orow = out + ((size_t)b * N + i) * 14;
#pragma unroll
    for (int e = 0; e < 14; e++) {
        float o = sbo[e];
#pragma unroll
        for (int f = 0; f < 14; f++) o = fmaf(sWo[e * 14 + f], pre[f], o);
        orow[e] = o;
    }
    float cu = 1.f / (1.f + __expf(ent - 6.9314718f));   // sigmoid(log(1024) - ent)
    out_cert[b * N + i] = fmaxf(cert[b * N + i], cu);
}

// ---------------- Sinkhorn in scaling-vector form ----------------
__global__ void sink_init_kernel() {
    int j = blockIdx.x * 1024 + threadIdx.x;
    g_r[j] = 1.f; g_c[j] = 1.f;
}

// row pass: u_i = sum_j P0_ij c_j ; r_i <- r_i / (r_i u_i + eps). grid (128,64) block 256
__global__ __launch_bounds__(256) void sink_row_kernel() {
    int b = blockIdx.y;
    __shared__ float scm[1024];
    for (int idx = threadIdx.x; idx < 1024; idx += 256) scm[idx] = g_c[b * 1024 + idx];
    __syncthreads();
    int w = threadIdx.x >> 5, lane = threadIdx.x & 31;
    int i = blockIdx.x * 8 + w;
    const float4* row = (const float4*)(g_P0 + ((size_t)b * N + i) * N);
    const float4* c4 = (const float4*)scm;
    float acc = 0.f;
#pragma unroll
    for (int k = 0; k < 8; k++) {
        float4 p = row[lane + 32 * k], cc = c4[lane + 32 * k];
        acc = fmaf(p.x, cc.x, fmaf(p.y, cc.y, fmaf(p.z, cc.z, fmaf(p.w, cc.w, acc))));
    }
#pragma unroll
    for (int off = 16; off; off >>= 1) acc += __shfl_xor_sync(0xffffffffu, acc, off);
    if (lane == 0) {
        float r = g_r[b * 1024 + i];
        g_r[b * 1024 + i] = r / fmaf(r, acc, SEPS);
    }
}

// col pass: vpart[s] = partial_i r_i P0_ij (deterministic partials). grid (8,64) block 1024
__global__ __launch_bounds__(1024) void sink_col_kernel() {
    int b = blockIdx.y, s = blockIdx.x;
    __shared__ float sr[128];
    int tid = threadIdx.x;
    if (tid < 128) sr[tid] = g_r[b * 1024 + s * 128 + tid];
    __syncthreads();
    const float* base = g_P0 + ((size_t)b * N + s * 128) * N + tid;
    float acc = 0.f;
#pragma unroll 4
    for (int i = 0; i < 128; i++) acc = fmaf(sr[i], base[(size_t)i * N], acc);
    g_vpart[(size_t)s * (B * N) + b * 1024 + tid] = acc;
}

// c update: c_j <- c_j / (c_j v_j + eps)
__global__ void sink_cupd_kernel() {
    int j = blockIdx.x * 1024 + threadIdx.x;
    float v = 0.f;
#pragma unroll
    for (int s = 0; s < 8; s++) v += g_vpart[(size_t)s * (B * N) + j];
    float c = g_c[j];
    g_c[j] = c / fmaf(c, v, SEPS);
}

// final: apply last c update inline, argmax_j P0_ij * c_j, gather permutation
__global__ __launch_bounds__(256) void sink_argmax_kernel(const int* __restrict__ perm,
                                                          float* __restrict__ out_perm) {
    int b = blockIdx.y;
    __shared__ float scm[1024];
    for (int idx = threadIdx.x; idx < 1024; idx += 256) {
        float v = 0.f;
#pragma unroll
        for (int s = 0; s < 8; s++) v += g_vpart[(size_t)s * (B * N) + b * 1024 + idx];
        float c = g_c[b * 1024 + idx];
        scm[idx] = c / fmaf(c, v, SEPS);
    }
    __syncthreads();
    int w = threadIdx.x >> 5, lane = threadIdx.x & 31;
    int i = blockIdx.x * 8 + w;
    const float* row = g_P0 + ((size_t)b * N + i) * N;
    float best = -1.f; int bi = 1024;
    for (int j = lane; j < 1024; j += 32) {
        float val = row[j] * scm[j];
        if (val > best) { best = val; bi = j; }
    }
#pragma unroll
    for (int off = 16; off; off >>= 1) {
        float ov = __shfl_xor_sync(0xffffffffu, best, off);
        int   oi = __shfl_xor_sync(0xffffffffu, bi, off);
        if (ov > best || (ov == best && oi < bi)) { best = ov; bi = oi; }
    }
    if (lane == 0) out_perm[b * 1024 + i] = (float)perm[b * 1024 + bi];
}

// ---------------- launch ----------------
extern "C" void kernel_launch(void* const* d_in, const int* in_sizes, int n_in,
                              void* d_out, int out_size) {
    const float* x    = (const float*)d_in[0];
    const float* cert = (const float*)d_in[1];
    const int*   perm = (const int*)d_in[2];
    const float* Wq = (const float*)d_in[3];  const float* bq = (const float*)d_in[4];
    const float* Wk = (const float*)d_in[5];  const float* bk = (const float*)d_in[6];
    const float* Wv = (const float*)d_in[7];  const float* bv = (const float*)d_in[8];
    const float* Wo = (const float*)d_in[9];  const float* bo = (const float*)d_in[10];

    float* out      = (float*)d_out;                       // (b,n,14)
    float* out_cert = out + (size_t)B * N * D;             // (b,n)
    float* out_perm = out_cert + (size_t)B * N;            // (b,n) as float

    qkv_kernel<<<256, 256>>>(x, Wq, bq, Wk, bk, Wv, bv);
    attn_kernel<<<dim3(8, 64), 128>>>(cert, Wo, bo, out, out_cert);
    sink_init_kernel<<<64, 1024>>>();
    for (int t = 0; t < 20; t++) {
        if (t) sink_cupd_kernel<<<64, 1024>>>();
        sink_row_kernel<<<dim3(128, 64), 256>>>();
        sink_col_kernel<<<dim3(8, 64), 1024>>>();
    }
    sink_argmax_kernel<<<dim3(128, 64), 256>>>(perm, out_perm);
}

// round 3
// speedup vs baseline: 1.3482x; 1.3482x over previous
#include <cuda_runtime.h>

#define B 64
#define N 1024
#define D 14
#define HDP 8          // head dim padded 7 -> 8
#define SEPS 1e-10f
#define NSLAB 128      // row-slabs per matrix in fused sinkhorn (8 rows each)

// ---------------- device scratch (static globals: allowed) ----------------
__device__ float g_P0[(size_t)B * N * N];        // 256 MB: (avg_attn + eps)^10
__device__ float g_Q[B * 2 * N * HDP];           // (b,h,n,8)
__device__ float g_K[B * 2 * N * HDP];
__device__ float g_V[B * 2 * N * HDP];
__device__ float g_r[B * N];
__device__ float g_c[B * N];
__device__ float g_vpart[(size_t)NSLAB * B * N]; // deterministic col-sum partials (33.5 MB)

// ---------------- helpers ----------------
__device__ __forceinline__ float dot8(float4 a, float4 b, float4 c, float4 d) {
    return fmaf(a.x, b.x, fmaf(a.y, b.y, fmaf(a.z, b.z, fmaf(a.w, b.w,
           fmaf(c.x, d.x, fmaf(c.y, d.y, fmaf(c.z, d.z, c.w * d.w)))))));
}
__device__ __forceinline__ float4 fma4(float s, float4 v, float4 acc) {
    acc.x = fmaf(s, v.x, acc.x); acc.y = fmaf(s, v.y, acc.y);
    acc.z = fmaf(s, v.z, acc.z); acc.w = fmaf(s, v.w, acc.w);
    return acc;
}
__device__ __forceinline__ float dot4(float4 a, float4 b) {
    return fmaf(a.x, b.x, fmaf(a.y, b.y, fmaf(a.z, b.z, a.w * b.w)));
}

// ---------------- kernel 1: QKV projection ----------------
__global__ void qkv_kernel(const float* __restrict__ x,
                           const float* __restrict__ Wq, const float* __restrict__ bq,
                           const float* __restrict__ Wk, const float* __restrict__ bk,
                           const float* __restrict__ Wv, const float* __restrict__ bv) {
    __shared__ float w[3 * 196 + 3 * 14];
    int tid = threadIdx.x;
    for (int k = tid; k < 196; k += blockDim.x) {
        w[k] = Wq[k]; w[196 + k] = Wk[k]; w[392 + k] = Wv[k];
    }
    if (tid < 14) { w[588 + tid] = bq[tid]; w[602 + tid] = bk[tid]; w[616 + tid] = bv[tid]; }
    __syncthreads();

    int t = blockIdx.x * blockDim.x + tid;          // token index over B*N
    int b = t >> 10, i = t & 1023;
    float xv[14];
#pragma unroll
    for (int f = 0; f < 14; f++) xv[f] = x[(size_t)t * 14 + f];

#pragma unroll
    for (int e = 0; e < 14; e++) {
        float q = w[588 + e], k = w[602 + e], v = w[616 + e];
#pragma unroll
        for (int f = 0; f < 14; f++) {
            q = fmaf(w[e * 14 + f],       xv[f], q);
            k = fmaf(w[196 + e * 14 + f], xv[f], k);
            v = fmaf(w[392 + e * 14 + f], xv[f], v);
        }
        int h = e / 7, eh = e - h * 7;
        size_t idx = (((size_t)b * 2 + h) * N + i) * HDP + eh;
        g_Q[idx] = q; g_K[idx] = k; g_V[idx] = v;
    }
#pragma unroll
    for (int h = 0; h < 2; h++) {
        size_t idx = (((size_t)b * 2 + h) * N + i) * HDP + 7;
        g_Q[idx] = 0.f; g_K[idx] = 0.f; g_V[idx] = 0.f;
    }
}

// ---------------- kernel 2: fused attention + entropy/cert + P0 + out proj ----------------
__global__ __launch_bounds__(128) void attn_kernel(const float* __restrict__ cert,
                                                   const float* __restrict__ Wo,
                                                   const float* __restrict__ bo,
                                                   float* __restrict__ out,
                                                   float* __restrict__ out_cert) {
    __shared__ float sWo[196];
    __shared__ float sbo[16];
    __shared__ float stg[4][32][33];   // coalescing stage for P0 writes

    int tid = threadIdx.x, w = tid >> 5, lane = tid & 31;
    for (int k = tid; k < 196; k += 128) sWo[k] = Wo[k];
    if (tid < 14) sbo[tid] = bo[tid];
    __syncthreads();

    int b = blockIdx.y;
    int i = blockIdx.x * 128 + w * 32 + lane;

    const float4* Kb = (const float4*)(g_K + (size_t)b * 16384);
    const float4* Vb = (const float4*)(g_V + (size_t)b * 16384);
    const float4* Qb = (const float4*)(g_Q + (size_t)b * 16384);

    const float sc = rsqrtf(7.0f);
    float4 q0a = Qb[2 * i], q0b = Qb[2 * i + 1];
    float4 q1a = Qb[2048 + 2 * i], q1b = Qb[2048 + 2 * i + 1];
    q0a.x *= sc; q0a.y *= sc; q0a.z *= sc; q0a.w *= sc;
    q0b.x *= sc; q0b.y *= sc; q0b.z *= sc; q0b.w *= sc;
    q1a.x *= sc; q1a.y *= sc; q1a.z *= sc; q1a.w *= sc;
    q1b.x *= sc; q1b.y *= sc; q1b.z *= sc; q1b.w *= sc;

    // pass 1: softmax denominators (scores ~N(0,1): exp without max-shift is safe)
    float Z0 = 0.f, Z1 = 0.f;
#pragma unroll 2
    for (int j = 0; j < 1024; j++) {
        Z0 += __expf(dot8(q0a, Kb[2 * j], q0b, Kb[2 * j + 1]));
        Z1 += __expf(dot8(q1a, Kb[2048 + 2 * j], q1b, Kb[2048 + 2 * j + 1]));
    }
    float inv0 = 1.f / Z0, inv1 = 1.f / Z1;

    // pass 2: probs, entropy, P0 = (avg+eps)^10, attn @ V
    float4 a0 = make_float4(0.f, 0.f, 0.f, 0.f), b0v = a0, a1 = a0, b1v = a0;
    float ent = 0.f;
    float* srow = &stg[w][lane][0];
    size_t prow_base = ((size_t)b * N + (size_t)blockIdx.x * 128 + w * 32) * N;

    for (int jc = 0; jc < 1024; jc += 32) {
#pragma unroll 4
        for (int jj = 0; jj < 32; jj++) {
            int j = jc + jj;
            float p0 = __expf(dot8(q0a, Kb[2 * j], q0b, Kb[2 * j + 1])) * inv0;
            float p1 = __expf(dot8(q1a, Kb[2048 + 2 * j], q1b, Kb[2048 + 2 * j + 1])) * inv1;
            float a = 0.5f * (p0 + p1);
            float t = a + SEPS;
            ent -= a * __logf(t);
            float t2 = t * t;
            float t4 = t2 * t2;
            srow[jj] = t4 * t4 * t2;          // t^10
            a0  = fma4(p0, Vb[2 * j], a0);
            b0v = fma4(p0, Vb[2 * j + 1], b0v);
            a1  = fma4(p1, Vb[2048 + 2 * j], a1);
            b1v = fma4(p1, Vb[2048 + 2 * j + 1], b1v);
        }
        __syncwarp();
#pragma unroll 8
        for (int r = 0; r < 32; r++)
            g_P0[prow_base + (size_t)r * N + jc + lane] = stg[w][r][lane];
        __syncwarp();
    }

    // epilogue: out = pre @ Wo.T + bo ; certainty update
    float pre[14] = {a0.x, a0.y, a0.z, a0.w, b0v.x, b0v.y, b0v.z,
                     a1.x, a1.y, a1.z, a1.w, b1v.x, b1v.y, b1v.z};
    float* orow = out + ((size_t)b * N + i) * 14;
#pragma unroll
    for (int e = 0; e < 14; e++) {
        float o = sbo[e];
#pragma unroll
        for (int f = 0; f < 14; f++) o = fmaf(sWo[e * 14 + f], pre[f], o);
        orow[e] = o;
    }
    float cu = 1.f / (1.f + __expf(ent - 6.9314718f));   // sigmoid(log(1024) - ent)
    out_cert[b * N + i] = fmaxf(cert[b * N + i], cu);
}

// ---------------- Sinkhorn: fused row+col pass (ONE read of P0 per iteration) ----------------
__global__ void sink_init_kernel() {
    int j = blockIdx.x * 1024 + threadIdx.x;
    g_r[j] = 1.f; g_c[j] = 1.f;
}

// One iteration: u_i = row_i . c ; r_i <- r_i/(r_i u_i + eps) ; vpart[s] = sum_i r'_i P0_ij.
// grid (NSLAB=128, B=64), block 256. Each block owns 8 rows; P0 slab held in registers.
__global__ __launch_bounds__(256) void sink_fused_kernel() {
    int b = blockIdx.y, s = blockIdx.x;
    int tid = threadIdx.x, w = tid >> 5, lane = tid & 31;
    __shared__ float su[8][8];   // [row][warp] partial u
    __shared__ float sr[8];      // updated r' for the 8 rows

    // c chunk: thread tid owns columns 4*tid .. 4*tid+3
    float4 c4 = ((const float4*)(g_c + b * 1024))[tid];

    // load 8-row slab: 8 independent LDG.128 (high MLP), coalesced per row
    const float4* base = (const float4*)(g_P0 + ((size_t)b * N + (size_t)s * 8) * N);
    float4 p[8];
#pragma unroll
    for (int i = 0; i < 8; i++) p[i] = base[(size_t)i * 256 + tid];

    // phase A: u_i = sum_j P0_ij c_j  (warp reduce -> smem -> 8 threads finish)
#pragma unroll
    for (int i = 0; i < 8; i++) {
        float t = dot4(p[i], c4);
#pragma unroll
        for (int off = 16; off; off >>= 1) t += __shfl_xor_sync(0xffffffffu, t, off);
        if (lane == 0) su[i][w] = t;
    }
    __syncthreads();
    if (tid < 8) {
        float u = 0.f;
#pragma unroll
        for (int k = 0; k < 8; k++) u += su[tid][k];
        int ri = b * 1024 + s * 8 + tid;
        float r = g_r[ri];
        r = r / fmaf(r, u, SEPS);
        g_r[ri] = r;
        sr[tid] = r;
    }
    __syncthreads();

    // phase B: column partials with the UPDATED r (pure register math)
    float4 v = make_float4(0.f, 0.f, 0.f, 0.f);
#pragma unroll
    for (int i = 0; i < 8; i++) v = fma4(sr[i], p[i], v);
    ((float4*)(g_vpart + ((size_t)s * B + b) * N))[tid] = v;
}

// c update: c_j <- c_j / (c_j v_j + eps), v = deterministic sum of 128 partial slabs
__global__ void sink_cupd_kernel() {
    int b = blockIdx.x, idx = threadIdx.x;
    float v = 0.f;
#pragma unroll 8
    for (int s = 0; s < NSLAB; s++) v += g_vpart[((size_t)s * B + b) * N + idx];
    int j = b * 1024 + idx;
    float c = g_c[j];
    g_c[j] = c / fmaf(c, v, SEPS);
}

// final: argmax_j P0_ij * c_j (r drops out of argmax), gather permutation
__global__ __launch_bounds__(256) void sink_argmax_kernel(const int* __restrict__ perm,
                                                          float* __restrict__ out_perm) {
    int b = blockIdx.y;
    __shared__ float scm[1024];
    for (int idx = threadIdx.x; idx < 1024; idx += 256) scm[idx] = g_c[b * 1024 + idx];
    __syncthreads();
    int w = threadIdx.x >> 5, lane = threadIdx.x & 31;
    int i = blockIdx.x * 8 + w;
    const float* row = g_P0 + ((size_t)b * N + i) * N;
    float best = -1.f; int bi = 1024;
    for (int j = lane; j < 1024; j += 32) {
        float val = row[j] * scm[j];
        if (val > best) { best = val; bi = j; }
    }
#pragma unroll
    for (int off = 16; off; off >>= 1) {
        float ov = __shfl_xor_sync(0xffffffffu, best, off);
        int   oi = __shfl_xor_sync(0xffffffffu, bi, off);
        if (ov > best || (ov == best && oi < bi)) { best = ov; bi = oi; }
    }
    if (lane == 0) out_perm[b * 1024 + i] = (float)perm[b * 1024 + bi];
}

// ---------------- launch ----------------
extern "C" void kernel_launch(void* const* d_in, const int* in_sizes, int n_in,
                              void* d_out, int out_size) {
    const float* x    = (const float*)d_in[0];
    const float* cert = (const float*)d_in[1];
    const int*   perm = (const int*)d_in[2];
    const float* Wq = (const float*)d_in[3];  const float* bq = (const float*)d_in[4];
    const float* Wk = (const float*)d_in[5];  const float* bk = (const float*)d_in[6];
    const float* Wv = (const float*)d_in[7];  const float* bv = (const float*)d_in[8];
    const float* Wo = (const float*)d_in[9];  const float* bo = (const float*)d_in[10];

    float* out      = (float*)d_out;                       // (b,n,14)
    float* out_cert = out + (size_t)B * N * D;             // (b,n)
    float* out_perm = out_cert + (size_t)B * N;            // (b,n) as float

    qkv_kernel<<<256, 256>>>(x, Wq, bq, Wk, bk, Wv, bv);
    attn_kernel<<<dim3(8, 64), 128>>>(cert, Wo, bo, out, out_cert);
    sink_init_kernel<<<64, 1024>>>();
    for (int t = 0; t < 20; t++) {
        if (t) sink_cupd_kernel<<<64, 1024>>>();
        sink_fused_kernel<<<dim3(NSLAB, 64), 256>>>();
    }
    sink_cupd_kernel<<<64, 1024>>>();   // final c update (20th), so argmax reads finished c
    sink_argmax_kernel<<<dim3(128, 64), 256>>>(perm, out_perm);
}

// round 7
// speedup vs baseline: 1.4138x; 1.0487x over previous
#include <cuda_runtime.h>

#define B 64
#define N 1024
#define D 14
#define HDP 8          // head dim padded 7 -> 8
#define SEPS 1e-10f
#define NSLAB 128      // row-slabs per matrix in fused sinkhorn (8 rows each)

// ---------------- device scratch (static globals: allowed) ----------------
__device__ float g_P0[(size_t)B * N * N];        // 256 MB: (avg_attn + eps)^10
__device__ float g_Q[B * 2 * N * HDP];           // (b,h,n,8)
__device__ float g_K[B * 2 * N * HDP];
__device__ float g_V[B * 2 * N * HDP];
__device__ float g_r[B * N];
__device__ float g_c[B * N];
__device__ float g_vpart[(size_t)NSLAB * B * N]; // deterministic col-sum partials (33.5 MB)

// ---------------- helpers ----------------
__device__ __forceinline__ float dot8(float4 a, float4 b, float4 c, float4 d) {
    return fmaf(a.x, b.x, fmaf(a.y, b.y, fmaf(a.z, b.z, fmaf(a.w, b.w,
           fmaf(c.x, d.x, fmaf(c.y, d.y, fmaf(c.z, d.z, c.w * d.w)))))));
}
__device__ __forceinline__ float4 fma4(float s, float4 v, float4 acc) {
    acc.x = fmaf(s, v.x, acc.x); acc.y = fmaf(s, v.y, acc.y);
    acc.z = fmaf(s, v.z, acc.z); acc.w = fmaf(s, v.w, acc.w);
    return acc;
}
__device__ __forceinline__ float dot4(float4 a, float4 b) {
    return fmaf(a.x, b.x, fmaf(a.y, b.y, fmaf(a.z, b.z, a.w * b.w)));
}
__device__ __forceinline__ void barsync(int id, int cnt) {
    asm volatile("bar.sync %0, %1;" :: "r"(id), "r"(cnt) : "memory");
}

// ---------------- kernel 1: QKV projection ----------------
__global__ void qkv_kernel(const float* __restrict__ x,
                           const float* __restrict__ Wq, const float* __restrict__ bq,
                           const float* __restrict__ Wk, const float* __restrict__ bk,
                           const float* __restrict__ Wv, const float* __restrict__ bv) {
    __shared__ float w[3 * 196 + 3 * 14];
    int tid = threadIdx.x;
    for (int k = tid; k < 196; k += blockDim.x) {
        w[k] = Wq[k]; w[196 + k] = Wk[k]; w[392 + k] = Wv[k];
    }
    if (tid < 14) { w[588 + tid] = bq[tid]; w[602 + tid] = bk[tid]; w[616 + tid] = bv[tid]; }
    __syncthreads();

    int t = blockIdx.x * blockDim.x + tid;          // token index over B*N
    int b = t >> 10, i = t & 1023;
    float xv[14];
#pragma unroll
    for (int f = 0; f < 14; f++) xv[f] = x[(size_t)t * 14 + f];

#pragma unroll
    for (int e = 0; e < 14; e++) {
        float q = w[588 + e], k = w[602 + e], v = w[616 + e];
#pragma unroll
        for (int f = 0; f < 14; f++) {
            q = fmaf(w[e * 14 + f],       xv[f], q);
            k = fmaf(w[196 + e * 14 + f], xv[f], k);
            v = fmaf(w[392 + e * 14 + f], xv[f], v);
        }
        int h = e / 7, eh = e - h * 7;
        size_t idx = (((size_t)b * 2 + h) * N + i) * HDP + eh;
        g_Q[idx] = q; g_K[idx] = k; g_V[idx] = v;
    }
#pragma unroll
    for (int h = 0; h < 2; h++) {
        size_t idx = (((size_t)b * 2 + h) * N + i) * HDP + 7;
        g_Q[idx] = 0.f; g_K[idx] = 0.f; g_V[idx] = 0.f;
    }
}

// ---------------- kernel 2: fused attention (split-head) ----------------
// grid (8, 64), block 256 = 8 warps = 4 pairs. Pair p owns 32 queries;
// warp (p, h) handles head h for those queries. One thread = one (query, head).
__global__ __launch_bounds__(256) void attn_kernel(const float* __restrict__ cert,
                                                   const float* __restrict__ Wo,
                                                   const float* __restrict__ bo,
                                                   float* __restrict__ out,
                                                   float* __restrict__ out_cert) {
    __shared__ float sWo[196];
    __shared__ float sbo[16];
    __shared__ float ph[4][2][32][33];   // [pair][head][query][j]; head0 slab reused for t^10

    int tid = threadIdx.x, w = tid >> 5, lane = tid & 31;
    int pair = w >> 1, h = w & 1;
    for (int k = tid; k < 196; k += 256) sWo[k] = Wo[k];
    if (tid < 14) sbo[tid] = bo[tid];
    __syncthreads();

    int b = blockIdx.y;
    int q = blockIdx.x * 128 + pair * 32 + lane;    // this thread's query row

    const float4* Kh = (const float4*)(g_K + ((size_t)b * 2 + h) * 8192);
    const float4* Vh = (const float4*)(g_V + ((size_t)b * 2 + h) * 8192);
    const float4* Qh = (const float4*)(g_Q + ((size_t)b * 2 + h) * 8192);

    const float sc = rsqrtf(7.0f);
    float4 qa = Qh[2 * q], qb = Qh[2 * q + 1];
    qa.x *= sc; qa.y *= sc; qa.z *= sc; qa.w *= sc;
    qb.x *= sc; qb.y *= sc; qb.z *= sc; qb.w *= sc;

    // pass 1: softmax denominator for (q, h)
    float Z = 0.f;
#pragma unroll 4
    for (int j = 0; j < 1024; j++)
        Z += __expf(dot8(qa, Kh[2 * j], qb, Kh[2 * j + 1]));
    float inv = 1.f / Z;

    // pass 2
    float4 va = make_float4(0.f, 0.f, 0.f, 0.f), vb = va;
    float ent = 0.f;                                // this thread's half of entropy
    size_t prow_base = ((size_t)b * N + (size_t)blockIdx.x * 128 + pair * 32) * N;
    const int bar = 1 + pair;

    for (int jc = 0; jc < 1024; jc += 32) {
        // own-head probabilities for 32 keys + V accumulation
#pragma unroll 4
        for (int jj = 0; jj < 32; jj++) {
            int j = jc + jj;
            float p = __expf(dot8(qa, Kh[2 * j], qb, Kh[2 * j + 1])) * inv;
            ph[pair][h][lane][jj] = p;
            va = fma4(p, Vh[2 * j], va);
            vb = fma4(p, Vh[2 * j + 1], vb);
        }
        barsync(bar, 64);
        // combine: thread (h, lane) handles query=lane, jj in [16h, 16h+16)
#pragma unroll
        for (int k = 0; k < 16; k++) {
            int jj = h * 16 + k;
            float p0 = ph[pair][0][lane][jj];
            float p1 = ph[pair][1][lane][jj];
            float a = 0.5f * (p0 + p1);
            float t = a + SEPS;
            ent -= a * __logf(t);
            float t2 = t * t, t4 = t2 * t2;
            ph[pair][0][lane][jj] = t4 * t4 * t2;   // t^10, overwrites dead p0
        }
        barsync(bar, 64);
        // coalesced write: warp h stores rows [16h, 16h+16)
#pragma unroll
        for (int r2 = 0; r2 < 16; r2++) {
            int r = h * 16 + r2;
            g_P0[prow_base + (size_t)r * N + jc + lane] = ph[pair][0][r][lane];
        }
        barsync(bar, 64);
    }

    // epilogue: head-1 warp hands its V accums + entropy half to head-0 warp
    float* xch = &ph[pair][1][lane][0];             // ph free after last barrier
    if (h == 1) {
        xch[0] = va.x; xch[1] = va.y; xch[2] = va.z; xch[3] = va.w;
        xch[4] = vb.x; xch[5] = vb.y; xch[6] = vb.z;
        xch[8] = ent;
    }
    barsync(bar, 64);
    if (h == 0) {
        float pre[14] = {va.x, va.y, va.z, va.w, vb.x, vb.y, vb.z,
                         xch[0], xch[1], xch[2], xch[3], xch[4], xch[5], xch[6]};
        float* orow = out + ((size_t)b * N + q) * 14;
#pragma unroll
        for (int e = 0; e < 14; e++) {
            float o = sbo[e];
#pragma unroll
            for (int f = 0; f < 14; f++) o = fmaf(sWo[e * 14 + f], pre[f], o);
            orow[e] = o;
        }
        float entf = ent + xch[8];
        float cu = 1.f / (1.f + __expf(entf - 6.9314718f));  // sigmoid(log1024 - ent)
        out_cert[b * N + q] = fmaxf(cert[b * N + q], cu);
    }
}

// ---------------- Sinkhorn: fused row+col pass, streaming loads ----------------
// One iteration: u_i = row_i . c ; r_i <- r_i/(r_i u_i + eps) ; vpart = sum_i r'_i P0_ij
// grid (NSLAB=128, B=64), block 256. Slab = 8 rows; phase-B reload hits L1/L2.
template<bool FIRST>
__global__ __launch_bounds__(256) void sink_fused_kernel() {
    int b = blockIdx.y, s = blockIdx.x;
    int tid = threadIdx.x, w = tid >> 5, lane = tid & 31;
    __shared__ float su[8][8];
    __shared__ float sr[8];

    float4 c4 = FIRST ? make_float4(1.f, 1.f, 1.f, 1.f)
                      : ((const float4*)(g_c + b * 1024))[tid];

    const float4* base = (const float4*)(g_P0 + ((size_t)b * N + (size_t)s * 8) * N);

    // phase A: row dots (loads streamed, not held)
    float t[8];
#pragma unroll
    for (int i = 0; i < 8; i++) t[i] = dot4(base[(size_t)i * 256 + tid], c4);
#pragma unroll
    for (int i = 0; i < 8; i++) {
        float acc = t[i];
#pragma unroll
        for (int off = 16; off; off >>= 1) acc += __shfl_xor_sync(0xffffffffu, acc, off);
        if (lane == 0) su[i][w] = acc;
    }
    __syncthreads();
    if (tid < 8) {
        float u = 0.f;
#pragma unroll
        for (int k = 0; k < 8; k++) u += su[tid][k];
        int ri = b * 1024 + s * 8 + tid;
        float r = FIRST ? 1.f : g_r[ri];
        r = r / fmaf(r, u, SEPS);
        g_r[ri] = r;
        sr[tid] = r;
    }
    __syncthreads();

    // phase B: column partials with updated r (reloads hit L1/L2)
    float4 v = make_float4(0.f, 0.f, 0.f, 0.f);
#pragma unroll
    for (int i = 0; i < 8; i++) v = fma4(sr[i], base[(size_t)i * 256 + tid], v);
    ((float4*)(g_vpart + ((size_t)s * B + b) * N))[tid] = v;
}

// c update: c_j <- c_j / (c_j v_j + eps); v = deterministic sum of 128 slabs
template<bool FIRST>
__global__ void sink_cupd_kernel() {
    int b = blockIdx.x, tid = threadIdx.x;          // thread owns cols 4t..4t+3
    const float4* vp = (const float4*)(g_vpart) ;
    float4 v = make_float4(0.f, 0.f, 0.f, 0.f);
#pragma unroll 16
    for (int s = 0; s < NSLAB; s++) {
        float4 p = vp[((size_t)s * B + b) * 256 + tid];
        v.x += p.x; v.y += p.y; v.z += p.z; v.w += p.w;
    }
    float4 c = FIRST ? make_float4(1.f, 1.f, 1.f, 1.f)
                     : ((const float4*)(g_c + b * 1024))[tid];
    c.x = c.x / fmaf(c.x, v.x, SEPS);
    c.y = c.y / fmaf(c.y, v.y, SEPS);
    c.z = c.z / fmaf(c.z, v.z, SEPS);
    c.w = c.w / fmaf(c.w, v.w, SEPS);
    ((float4*)(g_c + b * 1024))[tid] = c;
}

// final: argmax_j P0_ij * c_j (r drops out), gather permutation
__global__ __launch_bounds__(256) void sink_argmax_kernel(const int* __restrict__ perm,
                                                          float* __restrict__ out_perm) {
    int b = blockIdx.y;
    __shared__ float scm[1024];
    for (int idx = threadIdx.x; idx < 1024; idx += 256) scm[idx] = g_c[b * 1024 + idx];
    __syncthreads();
    int w = threadIdx.x >> 5, lane = threadIdx.x & 31;
    int i = blockIdx.x * 8 + w;
    const float4* row4 = (const float4*)(g_P0 + ((size_t)b * N + i) * N);
    const float4* c4s = (const float4*)scm;
    float best = -1.f; int bi = 1024;
#pragma unroll
    for (int k = 0; k < 8; k++) {
        int j4 = lane + 32 * k;
        float4 p = row4[j4], c = c4s[j4];
        float v0 = p.x * c.x, v1 = p.y * c.y, v2 = p.z * c.z, v3 = p.w * c.w;
        if (v0 > best) { best = v0; bi = 4 * j4; }
        if (v1 > best) { best = v1; bi = 4 * j4 + 1; }
        if (v2 > best) { best = v2; bi = 4 * j4 + 2; }
        if (v3 > best) { best = v3; bi = 4 * j4 + 3; }
    }
#pragma unroll
    for (int off = 16; off; off >>= 1) {
        float ov = __shfl_xor_sync(0xffffffffu, best, off);
        int   oi = __shfl_xor_sync(0xffffffffu, bi, off);
        if (ov > best || (ov == best && oi < bi)) { best = ov; bi = oi; }
    }
    if (lane == 0) out_perm[b * 1024 + i] = (float)perm[b * 1024 + bi];
}

// ---------------- launch ----------------
extern "C" void kernel_launch(void* const* d_in, const int* in_sizes, int n_in,
                              void* d_out, int out_size) {
    const float* x    = (const float*)d_in[0];
    const float* cert = (const float*)d_in[1];
    const int*   perm = (const int*)d_in[2];
    const float* Wq = (const float*)d_in[3];  const float* bq = (const float*)d_in[4];
    const float* Wk = (const float*)d_in[5];  const float* bk = (const float*)d_in[6];
    const float* Wv = (const float*)d_in[7];  const float* bv = (const float*)d_in[8];
    const float* Wo = (const float*)d_in[9];  const float* bo = (const float*)d_in[10];

    float* out      = (float*)d_out;                       // (b,n,14)
    float* out_cert = out + (size_t)B * N * D;             // (b,n)
    float* out_perm = out_cert + (size_t)B * N;            // (b,n) as float

    qkv_kernel<<<256, 256>>>(x, Wq, bq, Wk, bk, Wv, bv);
    attn_kernel<<<dim3(8, 64), 256>>>(cert, Wo, bo, out, out_cert);

    sink_fused_kernel<true><<<dim3(NSLAB, 64), 256>>>();
    sink_cupd_kernel<true><<<64, 256>>>();
    for (int t = 1; t < 20; t++) {
        sink_fused_kernel<false><<<dim3(NSLAB, 64), 256>>>();
        sink_cupd_kernel<false><<<64, 256>>>();
    }
    sink_argmax_kernel<<<dim3(128, 64), 256>>>(perm, out_perm);
}

// round 9
// speedup vs baseline: 1.6918x; 1.1966x over previous
#include <cuda_runtime.h>

#define B 64
#define N 1024
#define D 14
#define HDP 8          // head dim padded 7 -> 8
#define SEPS 1e-10f
#define NSLAB 64       // row-slabs per matrix in fused sinkhorn (16 rows each)

// ---------------- device scratch (static globals: allowed) ----------------
__device__ float g_P0[(size_t)B * N * N];        // 256 MB: (avg_attn + eps)^10
__device__ float g_Q[B * 2 * N * HDP];           // (b,h,n,8)
__device__ float g_K[B * 2 * N * HDP];
__device__ float g_V[B * 2 * N * HDP];
__device__ float g_r[B * N];
__device__ float g_c[B * N];
__device__ float g_vpart[(size_t)NSLAB * B * N]; // deterministic col-sum partials (16.8 MB)

// ---------------- helpers ----------------
__device__ __forceinline__ float dot8(float4 a, float4 b, float4 c, float4 d) {
    return fmaf(a.x, b.x, fmaf(a.y, b.y, fmaf(a.z, b.z, fmaf(a.w, b.w,
           fmaf(c.x, d.x, fmaf(c.y, d.y, fmaf(c.z, d.z, c.w * d.w)))))));
}
__device__ __forceinline__ float4 fma4(float s, float4 v, float4 acc) {
    acc.x = fmaf(s, v.x, acc.x); acc.y = fmaf(s, v.y, acc.y);
    acc.z = fmaf(s, v.z, acc.z); acc.w = fmaf(s, v.w, acc.w);
    return acc;
}
__device__ __forceinline__ float dot4(float4 a, float4 b) {
    return fmaf(a.x, b.x, fmaf(a.y, b.y, fmaf(a.z, b.z, a.w * b.w)));
}
__device__ __forceinline__ void barsync(int id, int cnt) {
    asm volatile("bar.sync %0, %1;" :: "r"(id), "r"(cnt) : "memory");
}

// ---------------- kernel 1: QKV projection ----------------
__global__ void qkv_kernel(const float* __restrict__ x,
                           const float* __restrict__ Wq, const float* __restrict__ bq,
                           const float* __restrict__ Wk, const float* __restrict__ bk,
                           const float* __restrict__ Wv, const float* __restrict__ bv) {
    __shared__ float w[3 * 196 + 3 * 14];
    int tid = threadIdx.x;
    for (int k = tid; k < 196; k += blockDim.x) {
        w[k] = Wq[k]; w[196 + k] = Wk[k]; w[392 + k] = Wv[k];
    }
    if (tid < 14) { w[588 + tid] = bq[tid]; w[602 + tid] = bk[tid]; w[616 + tid] = bv[tid]; }
    __syncthreads();

    int t = blockIdx.x * blockDim.x + tid;          // token index over B*N
    int b = t >> 10, i = t & 1023;
    float xv[14];
#pragma unroll
    for (int f = 0; f < 14; f++) xv[f] = x[(size_t)t * 14 + f];

#pragma unroll
    for (int e = 0; e < 14; e++) {
        float q = w[588 + e], k = w[602 + e], v = w[616 + e];
#pragma unroll
        for (int f = 0; f < 14; f++) {
            q = fmaf(w[e * 14 + f],       xv[f], q);
            k = fmaf(w[196 + e * 14 + f], xv[f], k);
            v = fmaf(w[392 + e * 14 + f], xv[f], v);
        }
        int h = e / 7, eh = e - h * 7;
        size_t idx = (((size_t)b * 2 + h) * N + i) * HDP + eh;
        g_Q[idx] = q; g_K[idx] = k; g_V[idx] = v;
    }
#pragma unroll
    for (int h = 0; h < 2; h++) {
        size_t idx = (((size_t)b * 2 + h) * N + i) * HDP + 7;
        g_Q[idx] = 0.f; g_K[idx] = 0.f; g_V[idx] = 0.f;
    }
}

// ---------------- kernel 2: fused attention (split-head, log2 domain) ----------------
// grid (8, 64), block 256 = 8 warps = 4 pairs. Pair p owns 32 queries;
// warp (p, h) handles head h for those queries. One thread = one (query, head).
__global__ __launch_bounds__(256) void attn_kernel(const float* __restrict__ cert,
                                                   const float* __restrict__ Wo,
                                                   const float* __restrict__ bo,
                                                   float* __restrict__ out,
                                                   float* __restrict__ out_cert) {
    __shared__ float sWo[196];
    __shared__ float sbo[16];
    __shared__ float ph[4][2][32][33];   // [pair][head][query][j]; head0 slab reused for t^10

    int tid = threadIdx.x, w = tid >> 5, lane = tid & 31;
    int pair = w >> 1, h = w & 1;
    for (int k = tid; k < 196; k += 256) sWo[k] = Wo[k];
    if (tid < 14) sbo[tid] = bo[tid];
    __syncthreads();

    int b = blockIdx.y;
    int q = blockIdx.x * 128 + pair * 32 + lane;    // this thread's query row

    const float4* Kh = (const float4*)(g_K + ((size_t)b * 2 + h) * 8192);
    const float4* Vh = (const float4*)(g_V + ((size_t)b * 2 + h) * 8192);
    const float4* Qh = (const float4*)(g_Q + ((size_t)b * 2 + h) * 8192);

    // fold 1/sqrt(7) * log2(e) into q: scores live in log2 domain -> bare EX2
    const float sc = rsqrtf(7.0f) * 1.4426950408889634f;
    float4 qa = Qh[2 * q], qb = Qh[2 * q + 1];
    qa.x *= sc; qa.y *= sc; qa.z *= sc; qa.w *= sc;
    qb.x *= sc; qb.y *= sc; qb.z *= sc; qb.w *= sc;

    // pass 1: softmax denominator for (q, h)
    float Z = 0.f;
#pragma unroll 4
    for (int j = 0; j < 1024; j++)
        Z += exp2f(dot8(qa, Kh[2 * j], qb, Kh[2 * j + 1]));
    float inv = 1.f / Z;

    // pass 2
    float4 va = make_float4(0.f, 0.f, 0.f, 0.f), vb = va;
    float ent2 = 0.f;                               // entropy half, log2 units
    size_t prow_base = ((size_t)b * N + (size_t)blockIdx.x * 128 + pair * 32) * N;
    const int bar = 1 + pair;

    for (int jc = 0; jc < 1024; jc += 32) {
        // own-head probabilities for 32 keys + V accumulation
#pragma unroll 4
        for (int jj = 0; jj < 32; jj++) {
            int j = jc + jj;
            float p = exp2f(dot8(qa, Kh[2 * j], qb, Kh[2 * j + 1])) * inv;
            ph[pair][h][lane][jj] = p;
            va = fma4(p, Vh[2 * j], va);
            vb = fma4(p, Vh[2 * j + 1], vb);
        }
        barsync(bar, 64);
        // combine: thread (h, lane) handles query=lane, jj in [16h, 16h+16)
#pragma unroll
        for (int k = 0; k < 16; k++) {
            int jj = h * 16 + k;
            float p0 = ph[pair][0][lane][jj];
            float p1 = ph[pair][1][lane][jj];
            float a = 0.5f * (p0 + p1);
            float t = a + SEPS;
            ent2 -= a * __log2f(t);
            float t2 = t * t, t4 = t2 * t2;
            ph[pair][0][lane][jj] = t4 * t4 * t2;   // t^10, overwrites dead p0
        }
        barsync(bar, 64);
        // coalesced write: warp h stores rows [16h, 16h+16)
#pragma unroll
        for (int r2 = 0; r2 < 16; r2++) {
            int r = h * 16 + r2;
            g_P0[prow_base + (size_t)r * N + jc + lane] = ph[pair][0][r][lane];
        }
        barsync(bar, 64);
    }

    // epilogue: head-1 warp hands its V accums + entropy half to head-0 warp
    float* xch = &ph[pair][1][lane][0];             // ph free after last barrier
    if (h == 1) {
        xch[0] = va.x; xch[1] = va.y; xch[2] = va.z; xch[3] = va.w;
        xch[4] = vb.x; xch[5] = vb.y; xch[6] = vb.z;
        xch[8] = ent2;
    }
    barsync(bar, 64);
    if (h == 0) {
        float pre[14] = {va.x, va.y, va.z, va.w, vb.x, vb.y, vb.z,
                         xch[0], xch[1], xch[2], xch[3], xch[4], xch[5], xch[6]};
        float* orow = out + ((size_t)b * N + q) * 14;
#pragma unroll
        for (int e = 0; e < 14; e++) {
            float o = sbo[e];
#pragma unroll
            for (int f = 0; f < 14; f++) o = fmaf(sWo[e * 14 + f], pre[f], o);
            orow[e] = o;
        }
        float entf = (ent2 + xch[8]) * 0.69314718056f;       // back to nats
        float cu = 1.f / (1.f + __expf(entf - 6.9314718f));  // sigmoid(log1024 - ent)
        out_cert[b * N + q] = fmaxf(cert[b * N + q], cu);
    }
}

// ---------------- Sinkhorn: fused row+col pass, 16-row slabs ----------------
// u_i = row_i . c ; r_i <- r_i/(r_i u_i + eps) ; vpart[s] = sum_{i in slab} r'_i P0_ij
// grid (NSLAB=64, B=64), block 512 (two 256-thread halves of 8 rows each).
template<bool FIRST>
__global__ __launch_bounds__(512) void sink_fused_kernel() {
    int b = blockIdx.y, s = blockIdx.x;
    int tid = threadIdx.x;
    int half = tid >> 8, t8 = tid & 255;
    int w = tid >> 5, lane = tid & 31;
    __shared__ float su[16][8];
    __shared__ float sr[16];
    __shared__ float4 stage[256];

    float4 c4 = FIRST ? make_float4(1.f, 1.f, 1.f, 1.f)
                      : ((const float4*)(g_c + b * 1024))[t8];

    const float4* hb = (const float4*)(g_P0 + ((size_t)b * N + (size_t)s * 16) * N)
                       + (size_t)half * 8 * 256;

    // phase A: row dots (streamed, high MLP)
    float t[8];
#pragma unroll
    for (int i = 0; i < 8; i++) t[i] = dot4(hb[(size_t)i * 256 + t8], c4);
#pragma unroll
    for (int i = 0; i < 8; i++) {
        float acc = t[i];
#pragma unroll
        for (int off = 16; off; off >>= 1) acc += __shfl_xor_sync(0xffffffffu, acc, off);
        if (lane == 0) su[half * 8 + i][w & 7] = acc;
    }
    __syncthreads();
    if (tid < 16) {
        float u = 0.f;
#pragma unroll
        for (int k = 0; k < 8; k++) u += su[tid][k];
        int ri = b * 1024 + s * 16 + tid;
        float r = FIRST ? 1.f : g_r[ri];
        r = r / fmaf(r, u, SEPS);
        g_r[ri] = r;
        sr[tid] = r;
    }
    __syncthreads();

    // phase B: column partials with updated r (reloads hit L1/L2)
    float4 v = make_float4(0.f, 0.f, 0.f, 0.f);
#pragma unroll
    for (int i = 0; i < 8; i++) v = fma4(sr[half * 8 + i], hb[(size_t)i * 256 + t8], v);
    if (half == 1) stage[t8] = v;
    __syncthreads();
    if (half == 0) {
        float4 o = stage[t8];
        v.x += o.x; v.y += o.y; v.z += o.z; v.w += o.w;
        ((float4*)(g_vpart + ((size_t)s * B + b) * N))[t8] = v;
    }
}

// c update: c_j <- c_j / (c_j v_j + eps)
// grid (8 col-chunks, B), block 256 = 32 float4-cols x 8 slab-groups.
// Each thread sums 8 slabs; fixed-order group reduce in smem (deterministic).
template<bool FIRST>
__global__ __launch_bounds__(256) void sink_cupd_kernel() {
    int cb = blockIdx.x, b = blockIdx.y;
    int tid = threadIdx.x;
    int cf4 = tid & 31;          // float4-column within the 128-col chunk
    int g = tid >> 5;            // slab group 0..7
    __shared__ float4 sv[8][32];

    const float4* vp = (const float4*)g_vpart;
    int col4 = cb * 32 + cf4;
    float4 v = make_float4(0.f, 0.f, 0.f, 0.f);
#pragma unroll
    for (int k = 0; k < 8; k++) {
        int s = g * 8 + k;
        float4 p = vp[((size_t)s * B + b) * 256 + col4];
        v.x += p.x; v.y += p.y; v.z += p.z; v.w += p.w;
    }
    sv[g][cf4] = v;
    __syncthreads();
    if (g == 0) {
        v = sv[0][cf4];
#pragma unroll
        for (int k = 1; k < 8; k++) {
            float4 p = sv[k][cf4];
            v.x += p.x; v.y += p.y; v.z += p.z; v.w += p.w;
        }
        float4 c = FIRST ? make_float4(1.f, 1.f, 1.f, 1.f)
                         : ((const float4*)(g_c + b * 1024))[col4];
        c.x = c.x / fmaf(c.x, v.x, SEPS);
        c.y = c.y / fmaf(c.y, v.y, SEPS);
        c.z = c.z / fmaf(c.z, v.z, SEPS);
        c.w = c.w / fmaf(c.w, v.w, SEPS);
        ((float4*)(g_c + b * 1024))[col4] = c;
    }
}

// final: argmax_j P0_ij * c_j (r drops out), gather permutation
__global__ __launch_bounds__(256) void sink_argmax_kernel(const int* __restrict__ perm,
                                                          float* __restrict__ out_perm) {
    int b = blockIdx.y;
    __shared__ float scm[1024];
    for (int idx = threadIdx.x; idx < 1024; idx += 256) scm[idx] = g_c[b * 1024 + idx];
    __syncthreads();
    int w = threadIdx.x >> 5, lane = threadIdx.x & 31;
    int i = blockIdx.x * 8 + w;
    const float4* row4 = (const float4*)(g_P0 + ((size_t)b * N + i) * N);
    const float4* c4s = (const float4*)scm;
    float best = -1.f; int bi = 1024;
#pragma unroll
    for (int k = 0; k < 8; k++) {
        int j4 = lane + 32 * k;
        float4 p = row4[j4], c = c4s[j4];
        float v0 = p.x * c.x, v1 = p.y * c.y, v2 = p.z * c.z, v3 = p.w * c.w;
        if (v0 > best) { best = v0; bi = 4 * j4; }
        if (v1 > best) { best = v1; bi = 4 * j4 + 1; }
        if (v2 > best) { best = v2; bi = 4 * j4 + 2; }
        if (v3 > best) { best = v3; bi = 4 * j4 + 3; }
    }
#pragma unroll
    for (int off = 16; off; off >>= 1) {
        float ov = __shfl_xor_sync(0xffffffffu, best, off);
        int   oi = __shfl_xor_sync(0xffffffffu, bi, off);
        if (ov > best || (ov == best && oi < bi)) { best = ov; bi = oi; }
    }
    if (lane == 0) out_perm[b * 1024 + i] = (float)perm[b * 1024 + bi];
}

// ---------------- launch ----------------
extern "C" void kernel_launch(void* const* d_in, const int* in_sizes, int n_in,
                              void* d_out, int out_size) {
    const float* x    = (const float*)d_in[0];
    const float* cert = (const float*)d_in[1];
    const int*   perm = (const int*)d_in[2];
    const float* Wq = (const float*)d_in[3];  const float* bq = (const float*)d_in[4];
    const float* Wk = (const float*)d_in[5];  const float* bk = (const float*)d_in[6];
    const float* Wv = (const float*)d_in[7];  const float* bv = (const float*)d_in[8];
    const float* Wo = (const float*)d_in[9];  const float* bo = (const float*)d_in[10];

    float* out      = (float*)d_out;                       // (b,n,14)
    float* out_cert = out + (size_t)B * N * D;             // (b,n)
    float* out_perm = out_cert + (size_t)B * N;            // (b,n) as float

    qkv_kernel<<<256, 256>>>(x, Wq, bq, Wk, bk, Wv, bv);
    attn_kernel<<<dim3(8, 64), 256>>>(cert, Wo, bo, out, out_cert);

    sink_fused_kernel<true><<<dim3(NSLAB, 64), 512>>>();
    sink_cupd_kernel<true><<<dim3(8, 64), 256>>>();
    for (int t = 1; t < 20; t++) {
        sink_fused_kernel<false><<<dim3(NSLAB, 64), 512>>>();
        sink_cupd_kernel<false><<<dim3(8, 64), 256>>>();
    }
    sink_argmax_kernel<<<dim3(128, 64), 256>>>(perm, out_perm);
}